// round 15
// baseline (speedup 1.0000x reference)
#include <cuda_runtime.h>
#include <cuda_fp16.h>
#include <cstdint>

// Problem constants
#define NB   32      // batch
#define NN   1024    // nodes per graph
#define NF   128     // in features
#define NH   128     // hidden features

// fp16 scratch for support = fp16(x @ W)  (static -> allocation-guard safe)
__device__ __half g_support_h[(size_t)NB * NN * NH];   // 8 MB

// ===========================================================================
// PTX helpers (baseline sm_80-class instructions -> compile on compute_103)
// ===========================================================================
__device__ __forceinline__ uint32_t smem_to_u32(const void* p) {
    uint32_t a;
    asm("{ .reg .u64 t; cvta.to.shared.u64 t, %1; cvt.u32.u64 %0, t; }" : "=r"(a) : "l"(p));
    return a;
}

#define LDSM4(R, addr) \
    asm volatile("ldmatrix.sync.aligned.m8n8.x4.shared.b16 {%0,%1,%2,%3}, [%4];" \
        : "=r"((R)[0]), "=r"((R)[1]), "=r"((R)[2]), "=r"((R)[3]) : "r"(addr))

#define LDSM4T(R, addr) \
    asm volatile("ldmatrix.sync.aligned.m8n8.x4.trans.shared.b16 {%0,%1,%2,%3}, [%4];" \
        : "=r"((R)[0]), "=r"((R)[1]), "=r"((R)[2]), "=r"((R)[3]) : "r"(addr))

#define MMA16816(C, A, b0, b1) \
    asm volatile("mma.sync.aligned.m16n8k16.row.col.f32.f16.f16.f32 " \
        "{%0,%1,%2,%3},{%4,%5,%6,%7},{%8,%9},{%0,%1,%2,%3};" \
        : "+f"((C)[0]), "+f"((C)[1]), "+f"((C)[2]), "+f"((C)[3]) \
        : "r"((A)[0]), "r"((A)[1]), "r"((A)[2]), "r"((A)[3]), "r"(b0), "r"(b1))

__device__ __forceinline__ uint32_t pack_h2(__half a, __half b) {
    __half2 t = __halves2half2(a, b);
    return *reinterpret_cast<uint32_t*>(&t);
}

// fp32 -> (hi fp16, lo fp16) split of a float4
__device__ __forceinline__ void split4(float4 v, uint2& hu, uint2& lu) {
    __half h0 = __float2half_rn(v.x), h1 = __float2half_rn(v.y);
    __half h2 = __float2half_rn(v.z), h3 = __float2half_rn(v.w);
    __half l0 = __float2half_rn(v.x - __half2float(h0));
    __half l1 = __float2half_rn(v.y - __half2float(h1));
    __half l2 = __float2half_rn(v.z - __half2float(h2));
    __half l3 = __float2half_rn(v.w - __half2float(h3));
    hu.x = pack_h2(h0, h1); hu.y = pack_h2(h2, h3);
    lu.x = pack_h2(l0, l1); lu.y = pack_h2(l2, l3);
}

// fp32 -> hi fp16 only
__device__ __forceinline__ void split4hi(float4 v, uint2& hu) {
    hu.x = pack_h2(__float2half_rn(v.x), __float2half_rn(v.y));
    hu.y = pack_h2(__float2half_rn(v.z), __float2half_rn(v.w));
}

// Shared smem row strides
#define RSA   80        // A smem row stride bytes (32+8 halves)
#define RSB   272       // B smem row stride bytes (128+8 halves)

// ===========================================================================
// GEMM-1 (3-pass split-fp16): support_h = fp16(x @ W)
//   M-tile 64, 256 threads = 8 warps (2m x 4n), warp tile 32x32, BK=32, K=128.
//   (unchanged from round 14)
// ===========================================================================
#define G1_OAH   0
#define G1_OAL   5120               // 64*80
#define G1_OBH   10240
#define G1_OBL   18944              // +32*272
#define G1_STAGE 27648
#define G1_SMEM  (2*G1_STAGE + 256)

__global__ __launch_bounds__(256, 2)
void gemm1_kernel(const float* __restrict__ A,
                  const float* __restrict__ B,
                  __half* __restrict__ C)
{
    extern __shared__ char smem[];
    constexpr int NCH = NF / 32;   // 4

    const int tid = threadIdx.x;
    const int l   = tid & 31;
    const int wid = tid >> 5;      // 0..7
    const int wm  = wid >> 2;      // 0..1
    const int wn  = wid & 3;       // 0..3

    const float* Ag = A + (size_t)blockIdx.x * 64 * NF;
    __half*      Cg = C + (size_t)blockIdx.x * 64 * NH;

    const uint32_t sb = smem_to_u32(smem);

    float c[2][4][4];
    #pragma unroll
    for (int i = 0; i < 2; i++)
        #pragma unroll
        for (int j = 0; j < 4; j++)
            #pragma unroll
            for (int q = 0; q < 4; q++) c[i][j][q] = 0.0f;

    float4 pa[2], pb[4];

    auto loadA = [&](int k0) {
        #pragma unroll
        for (int s = 0; s < 2; s++) {
            int f = s * 256 + tid;
            int r = f >> 3, c4 = f & 7;
            pa[s] = *reinterpret_cast<const float4*>(Ag + (size_t)r * NF + k0 + c4 * 4);
        }
    };
    auto loadB = [&](int k0) {
        #pragma unroll
        for (int s = 0; s < 4; s++) {
            int f = s * 256 + tid;
            int r = f >> 5, c4 = f & 31;
            pb[s] = *reinterpret_cast<const float4*>(B + (size_t)(k0 + r) * NH + c4 * 4);
        }
    };
    auto storeStage = [&](int buf) {
        char* st = smem + buf * G1_STAGE;
        #pragma unroll
        for (int s = 0; s < 2; s++) {
            int f = s * 256 + tid;
            int r = f >> 3, c4 = f & 7;
            uint2 hu, lu; split4(pa[s], hu, lu);
            *reinterpret_cast<uint2*>(st + G1_OAH + r * RSA + c4 * 8) = hu;
            *reinterpret_cast<uint2*>(st + G1_OAL + r * RSA + c4 * 8) = lu;
        }
        #pragma unroll
        for (int s = 0; s < 4; s++) {
            int f = s * 256 + tid;
            int r = f >> 5, c4 = f & 31;
            uint2 hu, lu; split4(pb[s], hu, lu);
            *reinterpret_cast<uint2*>(st + G1_OBH + r * RSB + c4 * 8) = hu;
            *reinterpret_cast<uint2*>(st + G1_OBL + r * RSB + c4 * 8) = lu;
        }
    };
    auto compute = [&](int buf) {
        const uint32_t stg = sb + buf * G1_STAGE;
        #pragma unroll
        for (int ks = 0; ks < 2; ks++) {
            uint32_t ar = stg + G1_OAH + (uint32_t)(wm * 32 + (l & 15)) * RSA + ks * 32 + (l >> 4) * 16;
            uint32_t ah0[4], ah1[4], al0[4], al1[4];
            LDSM4(ah0, ar);
            LDSM4(ah1, ar + 16 * RSA);
            LDSM4(al0, ar + (G1_OAL - G1_OAH));
            LDSM4(al1, ar + (G1_OAL - G1_OAH) + 16 * RSA);
            uint32_t bh[2][4], bl[2][4];
            #pragma unroll
            for (int jp = 0; jp < 2; jp++) {
                uint32_t br = stg + G1_OBH + (uint32_t)(ks * 16 + (l & 15)) * RSB
                            + (uint32_t)(wn * 32 + jp * 16 + (l >> 4) * 8) * 2;
                LDSM4T(bh[jp], br);
                LDSM4T(bl[jp], br + (G1_OBL - G1_OBH));
            }
            #pragma unroll
            for (int jp = 0; jp < 2; jp++) {
                const int j0 = jp * 2, j1 = jp * 2 + 1;
                MMA16816(c[0][j0], ah0, bh[jp][0], bh[jp][1]);
                MMA16816(c[1][j0], ah1, bh[jp][0], bh[jp][1]);
                MMA16816(c[0][j1], ah0, bh[jp][2], bh[jp][3]);
                MMA16816(c[1][j1], ah1, bh[jp][2], bh[jp][3]);
                MMA16816(c[0][j0], ah0, bl[jp][0], bl[jp][1]);
                MMA16816(c[1][j0], ah1, bl[jp][0], bl[jp][1]);
                MMA16816(c[0][j1], ah0, bl[jp][2], bl[jp][3]);
                MMA16816(c[1][j1], ah1, bl[jp][2], bl[jp][3]);
                MMA16816(c[0][j0], al0, bh[jp][0], bh[jp][1]);
                MMA16816(c[1][j0], al1, bh[jp][0], bh[jp][1]);
                MMA16816(c[0][j1], al0, bh[jp][2], bh[jp][3]);
                MMA16816(c[1][j1], al1, bh[jp][2], bh[jp][3]);
            }
        }
    };

    loadA(0); loadB(0);
    storeStage(0);
    loadA(32); loadB(32);
    __syncthreads();

    for (int ch = 0; ch < NCH; ch++) {
        if (ch + 1 < NCH) storeStage((ch + 1) & 1);
        compute(ch & 1);
        if (ch + 2 < NCH) { loadA((ch + 2) * 32); loadB((ch + 2) * 32); }
        __syncthreads();
    }

    #pragma unroll
    for (int i = 0; i < 2; i++) {
        const int r0 = wm * 32 + i * 16 + (l >> 2);
        #pragma unroll
        for (int j = 0; j < 4; j++) {
            const int col = wn * 32 + j * 8 + (l & 3) * 2;
            __half2 h0 = __halves2half2(__float2half_rn(c[i][j][0]), __float2half_rn(c[i][j][1]));
            __half2 h1 = __halves2half2(__float2half_rn(c[i][j][2]), __float2half_rn(c[i][j][3]));
            *reinterpret_cast<__half2*>(Cg + (size_t)r0 * NH + col)       = h0;
            *reinterpret_cast<__half2*>(Cg + (size_t)(r0 + 8) * NH + col) = h1;
        }
    }
}

// ===========================================================================
// GEMM-2 (single-pass fp16): out = relu(adj @ support + b)
//   NEW SHAPE: M-tile 64, 256 threads = 8 warps (2m x 4n), warp tile 32x32,
//   BK=32, 2 CTAs/SM (launch_bounds(256,2); kernel needs ~94 regs < 128 cap).
//   Two independent barrier domains per SM: while one CTA drains its
//   __syncthreads, the other CTA's 8 warps keep issuing -> the per-chunk
//   barrier + LDSM->MMA ramp is no longer exposed.
//   Schedule unchanged (proven): LDG 2 chunks ahead, storeStage interleaved
//   with compute, plain loop, one sync/iter. B fp16 direct from gmem.
// ===========================================================================
#define G2_OA    0
#define G2_OB    5120               // A buf = 64*80
#define G2_STAGE 13824              // A+B per buffer (5120 + 8704)
#define G2_BIAS  (2*G2_STAGE)       // 27648
#define G2_SMEM  (G2_BIAS + 512)

__global__ __launch_bounds__(256, 2)
void gemm2_kernel(const float* __restrict__ adj,
                  const __half* __restrict__ Bh_g,
                  float* __restrict__ out,
                  const float* __restrict__ bias)
{
    extern __shared__ char smem[];
    constexpr int NCH = NN / 32;    // 32

    const int tid = threadIdx.x;
    const int l   = tid & 31;
    const int wid = tid >> 5;      // 0..7
    const int wm  = wid >> 2;      // 0..1
    const int wn  = wid & 3;       // 0..3
    const int b   = blockIdx.y;
    const int m0  = blockIdx.x * 64;

    const float*  Ag = adj  + (size_t)b * NN * NN + (size_t)m0 * NN;
    const __half* Bg = Bh_g + (size_t)b * NN * NH;
    float*        Cg = out  + (size_t)b * NN * NH + (size_t)m0 * NH;

    float* bias_s = reinterpret_cast<float*>(smem + G2_BIAS);
    if (tid < NH) bias_s[tid] = bias[tid];

    const uint32_t sb = smem_to_u32(smem);

    float c[2][4][4];
    #pragma unroll
    for (int i = 0; i < 2; i++)
        #pragma unroll
        for (int j = 0; j < 4; j++)
            #pragma unroll
            for (int q = 0; q < 4; q++) c[i][j][q] = 0.0f;

    float4 pa[2];   // A: 64x32 fp32 = 512 float4, 2/thread
    float4 pb[2];   // B: 32x128 fp16 = 8 KB = 512 float4, 2/thread

    auto loadA = [&](int k0) {
        #pragma unroll
        for (int s = 0; s < 2; s++) {
            int f = s * 256 + tid;
            int r = f >> 3, c4 = f & 7;        // r 0..63
            pa[s] = *reinterpret_cast<const float4*>(Ag + (size_t)r * NN + k0 + c4 * 4);
        }
    };
    auto loadB = [&](int k0) {
        #pragma unroll
        for (int s = 0; s < 2; s++) {
            int f = s * 256 + tid;
            int r = f >> 4, cq = f & 15;       // r 0..31, 16B chunk
            pb[s] = *reinterpret_cast<const float4*>(Bg + (size_t)(k0 + r) * NH + cq * 8);
        }
    };
    auto storeStage = [&](int buf) {
        char* st = smem + buf * G2_STAGE;
        #pragma unroll
        for (int s = 0; s < 2; s++) {
            int f = s * 256 + tid;
            int r = f >> 3, c4 = f & 7;
            uint2 hu; split4hi(pa[s], hu);
            *reinterpret_cast<uint2*>(st + G2_OA + r * RSA + c4 * 8) = hu;
        }
        #pragma unroll
        for (int s = 0; s < 2; s++) {
            int f = s * 256 + tid;
            int r = f >> 4, cq = f & 15;
            *reinterpret_cast<float4*>(st + G2_OB + r * RSB + cq * 16) = pb[s];
        }
    };
    auto compute = [&](int buf) {
        const uint32_t stg = sb + buf * G2_STAGE;
        #pragma unroll
        for (int ks = 0; ks < 2; ks++) {
            uint32_t ar = stg + G2_OA + (uint32_t)(wm * 32 + (l & 15)) * RSA + ks * 32 + (l >> 4) * 16;
            uint32_t ah0[4], ah1[4];
            LDSM4(ah0, ar);
            LDSM4(ah1, ar + 16 * RSA);
            uint32_t bh[2][4];
            #pragma unroll
            for (int jp = 0; jp < 2; jp++) {
                uint32_t br = stg + G2_OB + (uint32_t)(ks * 16 + (l & 15)) * RSB
                            + (uint32_t)(wn * 32 + jp * 16 + (l >> 4) * 8) * 2;
                LDSM4T(bh[jp], br);
            }
            #pragma unroll
            for (int jp = 0; jp < 2; jp++) {
                const int j0 = jp * 2, j1 = jp * 2 + 1;
                MMA16816(c[0][j0], ah0, bh[jp][0], bh[jp][1]);
                MMA16816(c[1][j0], ah1, bh[jp][0], bh[jp][1]);
                MMA16816(c[0][j1], ah0, bh[jp][2], bh[jp][3]);
                MMA16816(c[1][j1], ah1, bh[jp][2], bh[jp][3]);
            }
        }
    };

    // -------- pipeline: one __syncthreads per iteration, plain loop --------
    loadA(0); loadB(0);
    storeStage(0);
    loadA(32); loadB(32);
    __syncthreads();

    for (int ch = 0; ch < NCH; ch++) {
        if (ch + 1 < NCH) storeStage((ch + 1) & 1);
        compute(ch & 1);
        if (ch + 2 < NCH) { loadA((ch + 2) * 32); loadB((ch + 2) * 32); }
        __syncthreads();
    }

    // -------- epilogue --------
    #pragma unroll
    for (int i = 0; i < 2; i++) {
        const int r0 = wm * 32 + i * 16 + (l >> 2);
        #pragma unroll
        for (int j = 0; j < 4; j++) {
            const int col = wn * 32 + j * 8 + (l & 3) * 2;
            const float b0 = bias_s[col], b1 = bias_s[col + 1];
            float2 v0, v1;
            v0.x = fmaxf(c[i][j][0] + b0, 0.0f); v0.y = fmaxf(c[i][j][1] + b1, 0.0f);
            v1.x = fmaxf(c[i][j][2] + b0, 0.0f); v1.y = fmaxf(c[i][j][3] + b1, 0.0f);
            *reinterpret_cast<float2*>(Cg + (size_t)r0 * NH + col)       = v0;
            *reinterpret_cast<float2*>(Cg + (size_t)(r0 + 8) * NH + col) = v1;
        }
    }
}

// ===========================================================================
// Launch
// ===========================================================================
extern "C" void kernel_launch(void* const* d_in, const int* in_sizes, int n_in,
                              void* d_out, int out_size)
{
    const float* x   = (const float*)d_in[0];
    const float* adj = (const float*)d_in[1];
    const float* W   = (const float*)d_in[2];
    const float* b   = (const float*)d_in[3];
    float* out = (float*)d_out;

    __half* support = nullptr;
    cudaGetSymbolAddress((void**)&support, g_support_h);

    cudaFuncSetAttribute(gemm1_kernel,
                         cudaFuncAttributeMaxDynamicSharedMemorySize, G1_SMEM);
    cudaFuncSetAttribute(gemm2_kernel,
                         cudaFuncAttributeMaxDynamicSharedMemorySize, G2_SMEM);

    // GEMM-1: support_h = fp16(x @ W)   (x as flat [32768, 128]; 3-pass, M-tile 64)
    gemm1_kernel<<<dim3(NB * NN / 64, 1), 256, G1_SMEM>>>(x, W, support);

    // GEMM-2: out = relu(adj @ support + b)   (1-pass; M-tile 64, 2 CTAs/SM)
    gemm2_kernel<<<dim3(NN / 64, NB), 256, G2_SMEM>>>(adj, support, out, b);
}

// round 17
// speedup vs baseline: 1.3174x; 1.3174x over previous
#include <cuda_runtime.h>
#include <cuda_fp16.h>
#include <cstdint>

// Problem constants
#define NB   32      // batch
#define NN   1024    // nodes per graph
#define NF   128     // in features
#define NH   128     // hidden features

// fp16 scratch for support = fp16(x @ W)  (static -> allocation-guard safe)
__device__ __half g_support_h[(size_t)NB * NN * NH];   // 8 MB

// ===========================================================================
// PTX helpers (baseline sm_80-class instructions -> compile on compute_103)
// ===========================================================================
__device__ __forceinline__ uint32_t smem_to_u32(const void* p) {
    uint32_t a;
    asm("{ .reg .u64 t; cvta.to.shared.u64 t, %1; cvt.u32.u64 %0, t; }" : "=r"(a) : "l"(p));
    return a;
}

#define LDSM4(R, addr) \
    asm volatile("ldmatrix.sync.aligned.m8n8.x4.shared.b16 {%0,%1,%2,%3}, [%4];" \
        : "=r"((R)[0]), "=r"((R)[1]), "=r"((R)[2]), "=r"((R)[3]) : "r"(addr))

#define LDSM4T(R, addr) \
    asm volatile("ldmatrix.sync.aligned.m8n8.x4.trans.shared.b16 {%0,%1,%2,%3}, [%4];" \
        : "=r"((R)[0]), "=r"((R)[1]), "=r"((R)[2]), "=r"((R)[3]) : "r"(addr))

#define MMA16816(C, A, b0, b1) \
    asm volatile("mma.sync.aligned.m16n8k16.row.col.f32.f16.f16.f32 " \
        "{%0,%1,%2,%3},{%4,%5,%6,%7},{%8,%9},{%0,%1,%2,%3};" \
        : "+f"((C)[0]), "+f"((C)[1]), "+f"((C)[2]), "+f"((C)[3]) \
        : "r"((A)[0]), "r"((A)[1]), "r"((A)[2]), "r"((A)[3]), "r"(b0), "r"(b1))

__device__ __forceinline__ uint32_t pack_h2(__half a, __half b) {
    __half2 t = __halves2half2(a, b);
    return *reinterpret_cast<uint32_t*>(&t);
}

// fp32 -> hi fp16 of a float4
__device__ __forceinline__ void split4hi(float4 v, uint2& hu) {
    hu.x = pack_h2(__float2half_rn(v.x), __float2half_rn(v.y));
    hu.y = pack_h2(__float2half_rn(v.z), __float2half_rn(v.w));
}

// ===========================================================================
// GEMM-1 (single-pass fp16): support_h = fp16( fp16(x) @ fp16(W) )
//   M-tile 128, 256 threads = 8 warps (2m x 4n), warp tile 64x32.
//   K=128 entirely resident in smem -> ONE __syncthreads total, no pipeline.
//   2 CTAs/SM (regs ~100 < 128 cap; smem 2x68KB fits 227KB).
//   Error: support = comp(~2.8e-4) (+) fp16-round(2.0e-4) -> output ~3.9e-4,
//   2.5x inside the 1e-3 tolerance (the fp16 rounding of support already
//   floored accuracy; the dropped residual passes were nearly free precision-wise).
// ===========================================================================
#define S1_RS   272                 // 128 halves + 8 pad
#define S1_A    0
#define S1_W    34816               // 128*272
#define S1_SMEM 69632               // 2*34816

__global__ __launch_bounds__(256, 2)
void gemm1_kernel(const float* __restrict__ A,
                  const float* __restrict__ W,
                  __half* __restrict__ C)
{
    extern __shared__ char smem[];
    const int tid = threadIdx.x;
    const int l   = tid & 31;
    const int wid = tid >> 5;      // 0..7
    const int wm  = wid >> 2;      // 0..1
    const int wn  = wid & 3;       // 0..3

    const float* Ag = A + (size_t)blockIdx.x * 128 * NF;
    __half*      Cg = C + (size_t)blockIdx.x * 128 * NH;

    const uint32_t sb = smem_to_u32(smem);

    // ---- load x tile (128x128 fp32) and W (128x128 fp32), convert, STS.128 ----
    #pragma unroll
    for (int s = 0; s < 8; s++) {
        int g = s * 256 + tid;             // 0..2047 segments of 32B
        int r = g >> 4, c8 = (g & 15) * 8; // row, fp32 col base
        float4 v0 = *reinterpret_cast<const float4*>(Ag + (size_t)r * NF + c8);
        float4 v1 = *reinterpret_cast<const float4*>(Ag + (size_t)r * NF + c8 + 4);
        uint2 h0, h1; split4hi(v0, h0); split4hi(v1, h1);
        *reinterpret_cast<uint4*>(smem + S1_A + r * S1_RS + (g & 15) * 16) =
            make_uint4(h0.x, h0.y, h1.x, h1.y);
    }
    #pragma unroll
    for (int s = 0; s < 8; s++) {
        int g = s * 256 + tid;
        int r = g >> 4, c8 = (g & 15) * 8;
        float4 v0 = *reinterpret_cast<const float4*>(W + (size_t)r * NH + c8);
        float4 v1 = *reinterpret_cast<const float4*>(W + (size_t)r * NH + c8 + 4);
        uint2 h0, h1; split4hi(v0, h0); split4hi(v1, h1);
        *reinterpret_cast<uint4*>(smem + S1_W + r * S1_RS + (g & 15) * 16) =
            make_uint4(h0.x, h0.y, h1.x, h1.y);
    }
    __syncthreads();

    // ---- compute: 8 k16 steps over resident K=128 ----
    float c[4][4][4];
    #pragma unroll
    for (int i = 0; i < 4; i++)
        #pragma unroll
        for (int j = 0; j < 4; j++)
            #pragma unroll
            for (int q = 0; q < 4; q++) c[i][j][q] = 0.0f;

    #pragma unroll
    for (int ks = 0; ks < 8; ks++) {
        uint32_t ah[4][4];
        #pragma unroll
        for (int i = 0; i < 4; i++) {
            uint32_t ar = sb + S1_A + (uint32_t)(wm * 64 + i * 16 + (l & 15)) * S1_RS
                        + ks * 32 + (l >> 4) * 16;
            LDSM4(ah[i], ar);
        }
        uint32_t bh[2][4];
        #pragma unroll
        for (int jp = 0; jp < 2; jp++) {
            uint32_t br = sb + S1_W + (uint32_t)(ks * 16 + (l & 15)) * S1_RS
                        + (uint32_t)(wn * 32 + jp * 16 + (l >> 4) * 8) * 2;
            LDSM4T(bh[jp], br);
        }
        #pragma unroll
        for (int jp = 0; jp < 2; jp++)
            #pragma unroll
            for (int i = 0; i < 4; i++) {
                MMA16816(c[i][jp * 2],     ah[i], bh[jp][0], bh[jp][1]);
                MMA16816(c[i][jp * 2 + 1], ah[i], bh[jp][2], bh[jp][3]);
            }
    }

    // ---- epilogue: fp16 store ----
    #pragma unroll
    for (int i = 0; i < 4; i++) {
        const int r0 = wm * 64 + i * 16 + (l >> 2);
        #pragma unroll
        for (int j = 0; j < 4; j++) {
            const int col = wn * 32 + j * 8 + (l & 3) * 2;
            __half2 h0 = __halves2half2(__float2half_rn(c[i][j][0]), __float2half_rn(c[i][j][1]));
            __half2 h1 = __halves2half2(__float2half_rn(c[i][j][2]), __float2half_rn(c[i][j][3]));
            *reinterpret_cast<__half2*>(Cg + (size_t)r0 * NH + col)       = h0;
            *reinterpret_cast<__half2*>(Cg + (size_t)(r0 + 8) * NH + col) = h1;
        }
    }
}

// ===========================================================================
// GEMM-2 (single-pass fp16): out = relu(adj @ support + b)
//   Round-14 proven base (128x128 tile, 512 threads = 16 warps 4m x 4n,
//   warp tile 32x32, LDG 2 chunks ahead, storeStage interleaved with
//   compute, plain loop, one sync/iter) with two changes:
//     BK 32 -> 64 : halves barrier count (32 -> 16 iterations), doubles
//                   uninterrupted MMA bursts per sync.
//     STS.128 A   : each thread converts 2 adjacent float4 -> one 16B STS
//                   (halves A store ops on the busy L1/LSU path).
// ===========================================================================
#define RSA2     144                // A row: 64 halves + 8 pad
#define RSB2     272                // B row: 128 halves + 8 pad
#define G2_OA    0
#define G2_OB    18432              // 128*144
#define G2_STAGE 35840              // 18432 + 64*272
#define G2_BIAS  (2*G2_STAGE)       // 71680
#define G2_SMEM  (G2_BIAS + 512)    // 72192

__global__ __launch_bounds__(512, 1)
void gemm2_kernel(const float* __restrict__ adj,
                  const __half* __restrict__ Bh_g,
                  float* __restrict__ out,
                  const float* __restrict__ bias)
{
    extern __shared__ char smem[];
    constexpr int NCH = NN / 64;    // 16 chunks of BK=64

    const int tid = threadIdx.x;
    const int l   = tid & 31;
    const int wid = tid >> 5;
    const int wm  = wid >> 2;
    const int wn  = wid & 3;
    const int b   = blockIdx.y;
    const int m0  = blockIdx.x * 128;

    const float*  Ag = adj  + (size_t)b * NN * NN + (size_t)m0 * NN;
    const __half* Bg = Bh_g + (size_t)b * NN * NH;
    float*        Cg = out  + (size_t)b * NN * NH + (size_t)m0 * NH;

    float* bias_s = reinterpret_cast<float*>(smem + G2_BIAS);
    if (tid < NH) bias_s[tid] = bias[tid];

    const uint32_t sb = smem_to_u32(smem);

    float c[2][4][4];
    #pragma unroll
    for (int i = 0; i < 2; i++)
        #pragma unroll
        for (int j = 0; j < 4; j++)
            #pragma unroll
            for (int q = 0; q < 4; q++) c[i][j][q] = 0.0f;

    float4 pa[4];   // A: 128x64 fp32 = 2048 float4, 4/thread
    float4 pb[2];   // B: 64x128 fp16 = 16 KB = 1024 x 16B, 2/thread

    auto loadA = [&](int k0) {
        #pragma unroll
        for (int s = 0; s < 2; s++) {
            int g = s * 512 + tid;           // 32B segment id, 0..1023
            int r = g >> 3, c8 = (g & 7) * 8;
            pa[s * 2]     = *reinterpret_cast<const float4*>(Ag + (size_t)r * NN + k0 + c8);
            pa[s * 2 + 1] = *reinterpret_cast<const float4*>(Ag + (size_t)r * NN + k0 + c8 + 4);
        }
    };
    auto loadB = [&](int k0) {
        #pragma unroll
        for (int s = 0; s < 2; s++) {
            int g = s * 512 + tid;           // 16B segment id, 0..1023
            int r = g >> 4, cq = g & 15;
            pb[s] = *reinterpret_cast<const float4*>(Bg + (size_t)(k0 + r) * NH + cq * 8);
        }
    };
    auto storeStage = [&](int buf) {
        char* st = smem + buf * G2_STAGE;
        #pragma unroll
        for (int s = 0; s < 2; s++) {
            int g = s * 512 + tid;
            int r = g >> 3;
            uint2 h0, h1;
            split4hi(pa[s * 2], h0); split4hi(pa[s * 2 + 1], h1);
            *reinterpret_cast<uint4*>(st + G2_OA + r * RSA2 + (g & 7) * 16) =
                make_uint4(h0.x, h0.y, h1.x, h1.y);
        }
        #pragma unroll
        for (int s = 0; s < 2; s++) {
            int g = s * 512 + tid;
            int r = g >> 4, cq = g & 15;
            *reinterpret_cast<float4*>(st + G2_OB + r * RSB2 + cq * 16) = pb[s];
        }
    };
    auto compute = [&](int buf) {
        const uint32_t stg = sb + buf * G2_STAGE;
        #pragma unroll
        for (int ks = 0; ks < 4; ks++) {
            uint32_t ar = stg + G2_OA + (uint32_t)(wm * 32 + (l & 15)) * RSA2
                        + ks * 32 + (l >> 4) * 16;
            uint32_t ah0[4], ah1[4];
            LDSM4(ah0, ar);
            LDSM4(ah1, ar + 16 * RSA2);
            uint32_t bh[2][4];
            #pragma unroll
            for (int jp = 0; jp < 2; jp++) {
                uint32_t br = stg + G2_OB + (uint32_t)(ks * 16 + (l & 15)) * RSB2
                            + (uint32_t)(wn * 32 + jp * 16 + (l >> 4) * 8) * 2;
                LDSM4T(bh[jp], br);
            }
            #pragma unroll
            for (int jp = 0; jp < 2; jp++) {
                const int j0 = jp * 2, j1 = jp * 2 + 1;
                MMA16816(c[0][j0], ah0, bh[jp][0], bh[jp][1]);
                MMA16816(c[1][j0], ah1, bh[jp][0], bh[jp][1]);
                MMA16816(c[0][j1], ah0, bh[jp][2], bh[jp][3]);
                MMA16816(c[1][j1], ah1, bh[jp][2], bh[jp][3]);
            }
        }
    };

    // -------- pipeline: one __syncthreads per iteration, plain loop --------
    loadA(0); loadB(0);
    storeStage(0);
    loadA(64); loadB(64);
    __syncthreads();

    for (int ch = 0; ch < NCH; ch++) {
        if (ch + 1 < NCH) storeStage((ch + 1) & 1);
        compute(ch & 1);
        if (ch + 2 < NCH) { loadA((ch + 2) * 64); loadB((ch + 2) * 64); }
        __syncthreads();
    }

    // -------- epilogue --------
    #pragma unroll
    for (int i = 0; i < 2; i++) {
        const int r0 = wm * 32 + i * 16 + (l >> 2);
        #pragma unroll
        for (int j = 0; j < 4; j++) {
            const int col = wn * 32 + j * 8 + (l & 3) * 2;
            const float b0 = bias_s[col], b1 = bias_s[col + 1];
            float2 v0, v1;
            v0.x = fmaxf(c[i][j][0] + b0, 0.0f); v0.y = fmaxf(c[i][j][1] + b1, 0.0f);
            v1.x = fmaxf(c[i][j][2] + b0, 0.0f); v1.y = fmaxf(c[i][j][3] + b1, 0.0f);
            *reinterpret_cast<float2*>(Cg + (size_t)r0 * NH + col)       = v0;
            *reinterpret_cast<float2*>(Cg + (size_t)(r0 + 8) * NH + col) = v1;
        }
    }
}

// ===========================================================================
// Launch
// ===========================================================================
extern "C" void kernel_launch(void* const* d_in, const int* in_sizes, int n_in,
                              void* d_out, int out_size)
{
    const float* x   = (const float*)d_in[0];
    const float* adj = (const float*)d_in[1];
    const float* W   = (const float*)d_in[2];
    const float* b   = (const float*)d_in[3];
    float* out = (float*)d_out;

    __half* support = nullptr;
    cudaGetSymbolAddress((void**)&support, g_support_h);

    cudaFuncSetAttribute(gemm1_kernel,
                         cudaFuncAttributeMaxDynamicSharedMemorySize, S1_SMEM);
    cudaFuncSetAttribute(gemm2_kernel,
                         cudaFuncAttributeMaxDynamicSharedMemorySize, G2_SMEM);

    // GEMM-1: support_h = fp16(x @ W)   (single-pass, K resident, 1 barrier)
    gemm1_kernel<<<dim3(NB * NN / 128, 1), 256, S1_SMEM>>>(x, W, support);

    // GEMM-2: out = relu(adj @ support + b)   (single-pass, BK=64)
    gemm2_kernel<<<dim3(NN / 128, NB), 512, G2_SMEM>>>(adj, support, out, b);
}